// round 15
// baseline (speedup 1.0000x reference)
#include <cuda_runtime.h>
#include <cuda_bf16.h>
#include <cstdint>

// Problem constants
constexpr int T_DIM = 256;
constexpr int B_DIM = 256;
constexpr int IN_DIM = 1024;
constexpr int H_DIM = 1024;
constexpr int M1 = T_DIM * B_DIM;
constexpr int BH = B_DIM * H_DIM;

// ---------------------------------------------------------------------------
// Device globals (static allocations - allowed)
// ---------------------------------------------------------------------------
__device__ int g_cnt[T_DIM];                       // per-step barrier counters
__device__ __nv_bfloat16 g_Wh_hi[H_DIM * H_DIM];   // Wh split hi
__device__ __nv_bfloat16 g_Wh_lo[H_DIM * H_DIM];   // Wh split lo
__device__ __nv_bfloat16 g_h_hi[2][BH];            // h split hi (step parity)
__device__ __nv_bfloat16 g_h_lo[2][BH];            // h split lo

constexpr int N_CTAS = 128;    // GLOBAL barrier (proven R3-R8, R11, R13)
constexpr int THREADS = 512;   // 16 warps: 2 m32-tiles x 8 k-eighths

// Shared memory layout (bytes) for the persistent kernel
// B (Wh slice) resident: [32 n][1032 k] bf16 per half (pad 8 -> 2064B rows)
constexpr int B_ROW_BYTES = 1032 * 2;                  // 2064
constexpr int SM_BHI = 0;
constexpr int SM_BLO = SM_BHI + 32 * B_ROW_BYTES;      // 66048
// A chunks: [64 rows][136 k] bf16 (pad 8 -> 272B rows), double buffered, hi+lo
constexpr int A_ROW_BYTES = 136 * 2;                   // 272
constexpr int A_BUF = 64 * A_ROW_BYTES;                // 17408
constexpr int SM_A_HI = SM_BLO + 32 * B_ROW_BYTES;     // 132096
constexpr int SM_A_LO = SM_A_HI + 2 * A_BUF;           // 166912
// 8-way k-reduction buffers (144B rows, 16-aligned), overlaying the A staging
// region (dead at reduction time; next staging is past the step barrier).
constexpr int RED_ROW_BYTES = 36 * 4;                  // 144 (16-aligned)
constexpr int QBUF_BYTES = 64 * RED_ROW_BYTES;         // 9216
constexpr int SM_RED = SM_A_HI;
constexpr int SMEM_P2_A = SM_A_LO + 2 * A_BUF;         // 201728 (staging end)
constexpr int SMEM_P2_R = SM_RED + 8 * QBUF_BYTES;     // 205824 (RED end)
constexpr int SMEM_P2 = (SMEM_P2_R > SMEM_P2_A) ? SMEM_P2_R : SMEM_P2_A;

// ---------------------------------------------------------------------------
// PTX helpers (baseline sm_103-legal: ldmatrix + mma.sync HMMA path)
// ---------------------------------------------------------------------------
__device__ __forceinline__ uint32_t smem_to_u32(const void* p) {
    uint32_t a;
    asm("{ .reg .u64 t; cvta.to.shared.u64 t, %1; cvt.u32.u64 %0, t; }"
        : "=r"(a) : "l"(p));
    return a;
}
__device__ __forceinline__ void ldsm4(uint32_t r[4], uint32_t addr) {
    asm volatile("ldmatrix.sync.aligned.m8n8.x4.shared.b16 {%0,%1,%2,%3}, [%4];"
                 : "=r"(r[0]), "=r"(r[1]), "=r"(r[2]), "=r"(r[3]) : "r"(addr));
}
__device__ __forceinline__ void mma_bf16(float d[4], const uint32_t a[4],
                                         const uint32_t b[2]) {
    asm("mma.sync.aligned.m16n8k16.row.col.f32.bf16.bf16.f32 "
        "{%0,%1,%2,%3}, {%4,%5,%6,%7}, {%8,%9}, {%0,%1,%2,%3};"
        : "+f"(d[0]), "+f"(d[1]), "+f"(d[2]), "+f"(d[3])
        : "r"(a[0]), "r"(a[1]), "r"(a[2]), "r"(a[3]), "r"(b[0]), "r"(b[1]));
}

// ---------------------------------------------------------------------------
// Packed f32x2 helpers (phase-1 GEMM)
// ---------------------------------------------------------------------------
__device__ __forceinline__ unsigned long long pack2(float lo, float hi) {
    unsigned long long r;
    asm("mov.b64 %0, {%1, %2};" : "=l"(r) : "f"(lo), "f"(hi));
    return r;
}
__device__ __forceinline__ unsigned long long ffma2(unsigned long long a,
                                                    unsigned long long b,
                                                    unsigned long long c) {
    unsigned long long d;
    asm("fma.rn.f32x2 %0, %1, %2, %3;" : "=l"(d) : "l"(a), "l"(b), "l"(c));
    return d;
}
__device__ __forceinline__ float2 unpack2(unsigned long long v) {
    float2 f;
    asm("mov.b64 {%0, %1}, %2;" : "=f"(f.x), "=f"(f.y) : "l"(v));
    return f;
}

// ---------------------------------------------------------------------------
// Setup kernels (full-coverage split, fixed in R11)
// ---------------------------------------------------------------------------
__global__ void reset_kernel() {
    if (threadIdx.x < T_DIM) g_cnt[threadIdx.x] = 0;
}

constexpr int SPLIT_WH_BLOCKS = (H_DIM * H_DIM) / 1024;  // 1024
constexpr int SPLIT_H0_BLOCKS = BH / 1024;               // 256

__global__ __launch_bounds__(256) void split_all_kernel(
    const float* __restrict__ W, const float* __restrict__ h0)
{
    const int b = blockIdx.x;
    if (b < SPLIT_WH_BLOCKS) {
        int i = (b * 256 + threadIdx.x) * 4;
        float4 w = *reinterpret_cast<const float4*>(W + i);
#pragma unroll
        for (int j = 0; j < 4; j++) {
            float v = (&w.x)[j];
            __nv_bfloat16 hi = __float2bfloat16(v);
            g_Wh_hi[i + j] = hi;
            g_Wh_lo[i + j] = __float2bfloat16(v - __bfloat162float(hi));
        }
    } else {
        int i = ((b - SPLIT_WH_BLOCKS) * 256 + threadIdx.x) * 4;
        float4 v4 = *reinterpret_cast<const float4*>(h0 + i);
#pragma unroll
        for (int j = 0; j < 4; j++) {
            float v = (&v4.x)[j];
            __nv_bfloat16 hi = __float2bfloat16(v);
            g_h_hi[0][i + j] = hi;
            g_h_lo[0][i + j] = __float2bfloat16(v - __bfloat162float(hi));
        }
    }
}

// ---------------------------------------------------------------------------
// Phase 1: xi = x @ Wi^T + (bi + bh)  (FFMA2 SGEMM; bh folded into the bias)
// ---------------------------------------------------------------------------
__global__ __launch_bounds__(256) void gemm_xi_kernel(
    const float* __restrict__ A, const float* __restrict__ Bw,
    const float* __restrict__ bias, const float* __restrict__ bias2,
    float* __restrict__ C)
{
    __shared__ float As[8][128];
    __shared__ float Bs[8][128];

    const int tid = threadIdx.x;
    const int m0 = blockIdx.y * 128;
    const int n0 = blockIdx.x * 128;
    const int tx = tid & 15;
    const int ty = tid >> 4;
    const int lr = tid >> 1;
    const int lc = (tid & 1) * 4;

    unsigned long long acc[8][4];
#pragma unroll
    for (int i = 0; i < 8; i++)
#pragma unroll
        for (int j = 0; j < 4; j++) acc[i][j] = 0ull;

    const float* aLoad = A + (size_t)(m0 + lr) * IN_DIM + lc;
    const float* bLoad = Bw + (size_t)(n0 + lr) * IN_DIM + lc;

    for (int k0 = 0; k0 < IN_DIM; k0 += 8) {
        float4 av = *reinterpret_cast<const float4*>(aLoad + k0);
        float4 bv = *reinterpret_cast<const float4*>(bLoad + k0);
        As[lc + 0][lr] = av.x; As[lc + 1][lr] = av.y;
        As[lc + 2][lr] = av.z; As[lc + 3][lr] = av.w;
        Bs[lc + 0][lr] = bv.x; Bs[lc + 1][lr] = bv.y;
        Bs[lc + 2][lr] = bv.z; Bs[lc + 3][lr] = bv.w;
        __syncthreads();

#pragma unroll
        for (int k = 0; k < 8; k++) {
            float4 a0 = *reinterpret_cast<const float4*>(&As[k][ty * 8]);
            float4 a1 = *reinterpret_cast<const float4*>(&As[k][ty * 8 + 4]);
            ulonglong2 b01 = *reinterpret_cast<const ulonglong2*>(&Bs[k][tx * 8]);
            ulonglong2 b23 = *reinterpret_cast<const ulonglong2*>(&Bs[k][tx * 8 + 4]);
            float a[8] = {a0.x, a0.y, a0.z, a0.w, a1.x, a1.y, a1.z, a1.w};
#pragma unroll
            for (int i = 0; i < 8; i++) {
                unsigned long long a2 = pack2(a[i], a[i]);
                acc[i][0] = ffma2(a2, b01.x, acc[i][0]);
                acc[i][1] = ffma2(a2, b01.y, acc[i][1]);
                acc[i][2] = ffma2(a2, b23.x, acc[i][2]);
                acc[i][3] = ffma2(a2, b23.y, acc[i][3]);
            }
        }
        __syncthreads();
    }

    float bb[8];
#pragma unroll
    for (int j = 0; j < 8; j++)
        bb[j] = bias[n0 + tx * 8 + j] + bias2[n0 + tx * 8 + j];

#pragma unroll
    for (int i = 0; i < 8; i++) {
        float c[8];
#pragma unroll
        for (int j = 0; j < 4; j++) {
            float2 v = unpack2(acc[i][j]);
            c[2 * j + 0] = v.x + bb[2 * j + 0];
            c[2 * j + 1] = v.y + bb[2 * j + 1];
        }
        float* cp = C + (size_t)(m0 + ty * 8 + i) * H_DIM + n0 + tx * 8;
        *reinterpret_cast<float4*>(cp + 0) = make_float4(c[0], c[1], c[2], c[3]);
        *reinterpret_cast<float4*>(cp + 4) = make_float4(c[4], c[5], c[6], c[7]);
    }
}

// ---------------------------------------------------------------------------
// Phase 2: persistent HMMA recurrence, 512 threads (16 warps).
// 128 CTAs (32 n-tiles x 4 m-tiles of 64x32). Warp w: m32 tile = w&1,
// k-eighth (16 k's per 128-k chunk) = w>>1. Per chunk each warp does ONE
// k16 step: 4 A ldsm + 4 B ldsm + 24 MMA. Total LDSM/MMA per CTA-step
// identical to R13, spread over 2x warps -> 4 warps/SMSP latency hiding.
// 8-way k-reduction via padded smem buffers; uniform 512-thread epilogue.
// ---------------------------------------------------------------------------
__global__ __launch_bounds__(THREADS, 1) void rnn_hmma(
    float* __restrict__ out)
{
    extern __shared__ char sm[];
    const uint32_t sb = smem_to_u32(sm);
    const int tid = threadIdx.x;
    const int wid = tid >> 5;
    const int lane = tid & 31;
    const int n0 = blockIdx.x * 32;
    const int m0 = blockIdx.y * 64;
    const int mt2 = wid & 1;    // m32 tile (rows mt2*32 .. +32)
    const int ke = wid >> 1;    // k-eighth within each 128-k chunk (0..7)
    const int g = lane >> 2;
    const int tig = lane & 3;

    // One-time: load resident Wh hi/lo slice [32n][1024k] into padded smem.
    for (int i = 0; i < 8; i++) {
        int u = tid + THREADS * i;           // 0..4095 uint4 units per half
        int n = u >> 7;                      // 0..31
        int kqd = (u & 127) * 8;             // 0..1016
        uint4 vh = *reinterpret_cast<const uint4*>(&g_Wh_hi[(size_t)(n0 + n) * H_DIM + kqd]);
        uint4 vl = *reinterpret_cast<const uint4*>(&g_Wh_lo[(size_t)(n0 + n) * H_DIM + kqd]);
        *reinterpret_cast<uint4*>(sm + SM_BHI + n * B_ROW_BYTES + kqd * 2) = vh;
        *reinterpret_cast<uint4*>(sm + SM_BLO + n * B_ROW_BYTES + kqd * 2) = vl;
    }
    __syncthreads();

    // ldmatrix lane-address components (proven mappings; k window = ke*16 k = 32B).
    const uint32_t aByte0 =
        (uint32_t)((mt2 * 32 + (lane & 7) + ((lane >> 3) & 1) * 8) * A_ROW_BYTES
                   + ((lane >> 4) & 1) * 16 + ke * 32);
    const uint32_t aByte1 = aByte0 + 16 * A_ROW_BYTES;
    const uint32_t bRow = (uint32_t)((lane & 7) + ((lane >> 4) & 1) * 8);
    const uint32_t bKof = ((lane >> 3) & 1) * 16;
    const uint32_t bByte0 = bRow * B_ROW_BYTES + bKof;
    const uint32_t bByte1 = (bRow + 16) * B_ROW_BYTES + bKof;

    // Uniform epilogue coordinates: 1 row x 4 cols per thread (512 threads).
    const int er = tid >> 3;             // 0..63
    const int ec = (tid & 7) * 4;        // col offset 0,4,...,28
    const int erow = m0 + er;

    for (int t = 0; t < T_DIM; t++) {
        const int pb = t & 1;
        const __nv_bfloat16* Ah = g_h_hi[pb] + (size_t)m0 * H_DIM;
        const __nv_bfloat16* Al = g_h_lo[pb] + (size_t)m0 * H_DIM;

        // Hoisted xi loads (DRAM latency hides under the whole kc loop).
        float* outT = out + (size_t)t * BH;
        float* xp = &outT[(size_t)erow * H_DIM + n0 + ec];
        const float4 xv = __ldcg(reinterpret_cast<const float4*>(xp));

        float d[2][4][4];
#pragma unroll
        for (int t2 = 0; t2 < 2; t2++)
#pragma unroll
            for (int nt = 0; nt < 4; nt++)
#pragma unroll
                for (int e = 0; e < 4; e++) d[t2][nt][e] = 0.0f;

        // Prefetch chunk 0 (A [64 rows][128 k] hi+lo, coalesced uint4; 2/thread)
        uint4 rh[2], rl[2];
#pragma unroll
        for (int i = 0; i < 2; i++) {
            int u = tid + THREADS * i;       // 0..1023
            int rrow = u >> 4;               // 0..63
            int kqd = (u & 15) * 8;          // 0..120
            rh[i] = *reinterpret_cast<const uint4*>(&Ah[(size_t)rrow * H_DIM + kqd]);
            rl[i] = *reinterpret_cast<const uint4*>(&Al[(size_t)rrow * H_DIM + kqd]);
        }

        for (int kc = 0; kc < 8; kc++) {
            const int buf = kc & 1;
            char* ah_s = sm + SM_A_HI + buf * A_BUF;
            char* al_s = sm + SM_A_LO + buf * A_BUF;
            // STS (conflict-free: contiguous 16B within padded rows)
#pragma unroll
            for (int i = 0; i < 2; i++) {
                int u = tid + THREADS * i;
                int rrow = u >> 4;
                int kqd = (u & 15) * 8;
                *reinterpret_cast<uint4*>(ah_s + rrow * A_ROW_BYTES + kqd * 2) = rh[i];
                *reinterpret_cast<uint4*>(al_s + rrow * A_ROW_BYTES + kqd * 2) = rl[i];
            }
            __syncthreads();
            // Prefetch next chunk (latency hidden by the mma work below)
            if (kc + 1 < 8) {
                const int kb = (kc + 1) * 128;
#pragma unroll
                for (int i = 0; i < 2; i++) {
                    int u = tid + THREADS * i;
                    int rrow = u >> 4;
                    int kqd = (u & 15) * 8;
                    rh[i] = *reinterpret_cast<const uint4*>(&Ah[(size_t)rrow * H_DIM + kb + kqd]);
                    rl[i] = *reinterpret_cast<const uint4*>(&Al[(size_t)rrow * H_DIM + kb + kqd]);
                }
            }
            // Compute this chunk: ONE k16 step on this warp's k-eighth.
            const uint32_t ah0 = sb + SM_A_HI + buf * A_BUF + aByte0;
            const uint32_t ah1 = sb + SM_A_HI + buf * A_BUF + aByte1;
            const uint32_t al0 = sb + SM_A_LO + buf * A_BUF + aByte0;
            const uint32_t al1 = sb + SM_A_LO + buf * A_BUF + aByte1;
            const uint32_t bkB = (uint32_t)(kc * 256 + ke * 32);
            {
                uint32_t a_hi0[4], a_hi1[4], a_lo0[4], a_lo1[4];
                uint32_t b_h[8], b_l[8];
                ldsm4(a_hi0, ah0);
                ldsm4(a_hi1, ah1);
                ldsm4(a_lo0, al0);
                ldsm4(a_lo1, al1);
                ldsm4(b_h,     sb + SM_BHI + bByte0 + bkB);
                ldsm4(b_h + 4, sb + SM_BHI + bByte1 + bkB);
                ldsm4(b_l,     sb + SM_BLO + bByte0 + bkB);
                ldsm4(b_l + 4, sb + SM_BLO + bByte1 + bkB);
                // Term-major: hi*hi (8), lo*hi (8), hi*lo (8)
#pragma unroll
                for (int nt = 0; nt < 4; nt++) {
                    const uint32_t* ph = &b_h[(nt >> 1) * 4 + (nt & 1) * 2];
                    mma_bf16(d[0][nt], a_hi0, ph);
                    mma_bf16(d[1][nt], a_hi1, ph);
                }
#pragma unroll
                for (int nt = 0; nt < 4; nt++) {
                    const uint32_t* ph = &b_h[(nt >> 1) * 4 + (nt & 1) * 2];
                    mma_bf16(d[0][nt], a_lo0, ph);
                    mma_bf16(d[1][nt], a_lo1, ph);
                }
#pragma unroll
                for (int nt = 0; nt < 4; nt++) {
                    const uint32_t* pl = &b_l[(nt >> 1) * 4 + (nt & 1) * 2];
                    mma_bf16(d[0][nt], a_hi0, pl);
                    mma_bf16(d[1][nt], a_hi1, pl);
                }
            }
        }
        __syncthreads();

        // Publish all 8 k-eighth partials to padded smem buffers (8B aligned).
#pragma unroll
        for (int t2 = 0; t2 < 2; t2++)
#pragma unroll
            for (int nt = 0; nt < 4; nt++)
#pragma unroll
                for (int rp = 0; rp < 2; rp++) {
                    const int prow = mt2 * 32 + t2 * 16 + g + rp * 8;
                    *reinterpret_cast<float2*>(
                        sm + SM_RED + ke * QBUF_BYTES + prow * RED_ROW_BYTES
                        + (nt * 8 + tig * 2) * 4) =
                        make_float2(d[t2][nt][rp * 2], d[t2][nt][rp * 2 + 1]);
                }
        __syncthreads();

        // Uniform reduce + epilogue: each thread 1 row x 4 cols (16B aligned).
        {
            const int pb1 = pb ^ 1;
            float4 s = make_float4(0.f, 0.f, 0.f, 0.f);
#pragma unroll
            for (int q = 0; q < 8; q++) {
                const char* base = sm + SM_RED + q * QBUF_BYTES
                                 + er * RED_ROW_BYTES + ec * 4;
                float4 p = *reinterpret_cast<const float4*>(base);
                s.x += p.x; s.y += p.y; s.z += p.z; s.w += p.w;
            }
            float ov[4];
            ov[0] = tanhf(s.x + xv.x); ov[1] = tanhf(s.y + xv.y);
            ov[2] = tanhf(s.z + xv.z); ov[3] = tanhf(s.w + xv.w);

            *reinterpret_cast<float4*>(xp) = make_float4(ov[0], ov[1], ov[2], ov[3]);

            unsigned short hh[4], ll[4];
#pragma unroll
            for (int e = 0; e < 4; e++) {
                __nv_bfloat16 hb = __float2bfloat16(ov[e]);
                __nv_bfloat16 lb = __float2bfloat16(ov[e] - __bfloat162float(hb));
                hh[e] = *reinterpret_cast<unsigned short*>(&hb);
                ll[e] = *reinterpret_cast<unsigned short*>(&lb);
            }
            const size_t hoff = (size_t)erow * H_DIM + n0 + ec;
            *reinterpret_cast<uint2*>(&g_h_hi[pb1][hoff]) =
                *reinterpret_cast<const uint2*>(hh);
            *reinterpret_cast<uint2*>(&g_h_lo[pb1][hoff]) =
                *reinterpret_cast<const uint2*>(ll);
        }

        // GLOBAL device-wide step barrier (proven)
        if (t + 1 < T_DIM) {
            __syncthreads();
            __threadfence();
            if (tid == 0) {
                atomicAdd(&g_cnt[t], 1);
                volatile int* p = &g_cnt[t];
                while (*p < N_CTAS) { }
            }
            __syncthreads();
            __threadfence();
        }
    }
}

// ---------------------------------------------------------------------------
// Launch
// inputs: 0=x [T,B,IN], 1=h [B,H], 2=Wi_w [H,IN], 3=Wi_b [H],
//         4=Wh_w [H,H], 5=Wh_b [H];  output: hiddens [T,B,H]
// ---------------------------------------------------------------------------
extern "C" void kernel_launch(void* const* d_in, const int* in_sizes, int n_in,
                              void* d_out, int out_size) {
    const float* x   = (const float*)d_in[0];
    const float* h0  = (const float*)d_in[1];
    const float* Wi  = (const float*)d_in[2];
    const float* bi  = (const float*)d_in[3];
    const float* Wh  = (const float*)d_in[4];
    const float* bh  = (const float*)d_in[5];
    float* out = (float*)d_out;

    static bool attr_set = false;
    if (!attr_set) {
        cudaFuncSetAttribute(rnn_hmma,
                             cudaFuncAttributeMaxDynamicSharedMemorySize,
                             SMEM_P2);
        attr_set = true;
    }

    // Launch slot 1: reset counters; slot 2: split Wh+h0 (full coverage);
    // slot 3: xi GEMM; slot 4: rnn_hmma (the ncu-profiled slot).
    reset_kernel<<<1, 256>>>();
    split_all_kernel<<<SPLIT_WH_BLOCKS + SPLIT_H0_BLOCKS, 256>>>(Wh, h0);
    gemm_xi_kernel<<<dim3(H_DIM / 128, M1 / 128), 256>>>(x, Wi, bi, bh, out);
    rnn_hmma<<<dim3(32, 4), THREADS, SMEM_P2>>>(out);
}

// round 17
// speedup vs baseline: 1.5882x; 1.5882x over previous
#include <cuda_runtime.h>
#include <cuda_bf16.h>
#include <cstdint>

// Problem constants
constexpr int T_DIM = 256;
constexpr int B_DIM = 256;
constexpr int IN_DIM = 1024;
constexpr int H_DIM = 1024;
constexpr int M1 = T_DIM * B_DIM;
constexpr int BH = B_DIM * H_DIM;

// ---------------------------------------------------------------------------
// Device globals (static allocations - allowed)
// ---------------------------------------------------------------------------
__device__ int g_cnt[4 * T_DIM];                   // per-(m-group, step) counters
__device__ __nv_bfloat16 g_Wh_hi[H_DIM * H_DIM];   // Wh split hi
__device__ __nv_bfloat16 g_Wh_lo[H_DIM * H_DIM];   // Wh split lo
__device__ __nv_bfloat16 g_h_hi[2][BH];            // h split hi (step parity)
__device__ __nv_bfloat16 g_h_lo[2][BH];            // h split lo

// Row-independence: h_new[m,:] depends only on h[m,:] (and shared Wh), so the
// only sync needed is among the 32 CTAs covering the same 64 rows (one
// m-group). The 4 m-group chains are independent. (R9's group barrier was
// acquitted: the R9/R10 divergence was the under-sized h0 split grid, fixed
// in R11 -- byte-identical error with AND without the group barrier.)
constexpr int GRP_CTAS = 32;

// Shared memory layout (bytes) for the persistent kernel
// B (Wh slice) resident: [32 n][1032 k] bf16 per half (pad 8 -> 2064B rows)
constexpr int B_ROW_BYTES = 1032 * 2;                  // 2064
constexpr int SM_BHI = 0;
constexpr int SM_BLO = SM_BHI + 32 * B_ROW_BYTES;      // 66048
// A chunks: [64 rows][136 k] bf16 (pad 8 -> 272B rows), double buffered, hi+lo
constexpr int A_ROW_BYTES = 136 * 2;                   // 272
constexpr int A_BUF = 64 * A_ROW_BYTES;                // 17408
constexpr int SM_A_HI = SM_BLO + 32 * B_ROW_BYTES;     // 132096
constexpr int SM_A_LO = SM_A_HI + 2 * A_BUF;           // 166912
// 4-way k-reduction buffers (144B rows, 16-aligned), overlaying A staging
// (dead at reduction time; next staging is past the step barrier's sync).
constexpr int RED_ROW_BYTES = 36 * 4;                  // 144 (16-aligned)
constexpr int QBUF_BYTES = 64 * RED_ROW_BYTES;         // 9216
constexpr int SM_RED = SM_A_HI;
static_assert(4 * QBUF_BYTES <= 4 * A_BUF, "RED region fits in A staging");
constexpr int SMEM_P2 = SM_A_LO + 2 * A_BUF;           // 201728

// ---------------------------------------------------------------------------
// PTX helpers (baseline sm_103-legal: ldmatrix + mma.sync HMMA path)
// ---------------------------------------------------------------------------
__device__ __forceinline__ uint32_t smem_to_u32(const void* p) {
    uint32_t a;
    asm("{ .reg .u64 t; cvta.to.shared.u64 t, %1; cvt.u32.u64 %0, t; }"
        : "=r"(a) : "l"(p));
    return a;
}
__device__ __forceinline__ void ldsm4(uint32_t r[4], uint32_t addr) {
    asm volatile("ldmatrix.sync.aligned.m8n8.x4.shared.b16 {%0,%1,%2,%3}, [%4];"
                 : "=r"(r[0]), "=r"(r[1]), "=r"(r[2]), "=r"(r[3]) : "r"(addr));
}
__device__ __forceinline__ void mma_bf16(float d[4], const uint32_t a[4],
                                         const uint32_t b[2]) {
    asm("mma.sync.aligned.m16n8k16.row.col.f32.bf16.bf16.f32 "
        "{%0,%1,%2,%3}, {%4,%5,%6,%7}, {%8,%9}, {%0,%1,%2,%3};"
        : "+f"(d[0]), "+f"(d[1]), "+f"(d[2]), "+f"(d[3])
        : "r"(a[0]), "r"(a[1]), "r"(a[2]), "r"(a[3]), "r"(b[0]), "r"(b[1]));
}

// ---------------------------------------------------------------------------
// Packed f32x2 helpers (phase-1 GEMM)
// ---------------------------------------------------------------------------
__device__ __forceinline__ unsigned long long pack2(float lo, float hi) {
    unsigned long long r;
    asm("mov.b64 %0, {%1, %2};" : "=l"(r) : "f"(lo), "f"(hi));
    return r;
}
__device__ __forceinline__ unsigned long long ffma2(unsigned long long a,
                                                    unsigned long long b,
                                                    unsigned long long c) {
    unsigned long long d;
    asm("fma.rn.f32x2 %0, %1, %2, %3;" : "=l"(d) : "l"(a), "l"(b), "l"(c));
    return d;
}
__device__ __forceinline__ float2 unpack2(unsigned long long v) {
    float2 f;
    asm("mov.b64 {%0, %1}, %2;" : "=f"(f.x), "=f"(f.y) : "l"(v));
    return f;
}

// ---------------------------------------------------------------------------
// Setup kernels (full-coverage split; reset covers all 4*256 counters)
// ---------------------------------------------------------------------------
__global__ void reset_kernel() {
    int i = blockIdx.x * 256 + threadIdx.x;
    if (i < 4 * T_DIM) g_cnt[i] = 0;
}

constexpr int SPLIT_WH_BLOCKS = (H_DIM * H_DIM) / 1024;  // 1024
constexpr int SPLIT_H0_BLOCKS = BH / 1024;               // 256

__global__ __launch_bounds__(256) void split_all_kernel(
    const float* __restrict__ W, const float* __restrict__ h0)
{
    const int b = blockIdx.x;
    if (b < SPLIT_WH_BLOCKS) {
        int i = (b * 256 + threadIdx.x) * 4;
        float4 w = *reinterpret_cast<const float4*>(W + i);
#pragma unroll
        for (int j = 0; j < 4; j++) {
            float v = (&w.x)[j];
            __nv_bfloat16 hi = __float2bfloat16(v);
            g_Wh_hi[i + j] = hi;
            g_Wh_lo[i + j] = __float2bfloat16(v - __bfloat162float(hi));
        }
    } else {
        int i = ((b - SPLIT_WH_BLOCKS) * 256 + threadIdx.x) * 4;
        float4 v4 = *reinterpret_cast<const float4*>(h0 + i);
#pragma unroll
        for (int j = 0; j < 4; j++) {
            float v = (&v4.x)[j];
            __nv_bfloat16 hi = __float2bfloat16(v);
            g_h_hi[0][i + j] = hi;
            g_h_lo[0][i + j] = __float2bfloat16(v - __bfloat162float(hi));
        }
    }
}

// ---------------------------------------------------------------------------
// Phase 1: xi = x @ Wi^T + (bi + bh)  (FFMA2 SGEMM; bh folded into the bias)
// ---------------------------------------------------------------------------
__global__ __launch_bounds__(256) void gemm_xi_kernel(
    const float* __restrict__ A, const float* __restrict__ Bw,
    const float* __restrict__ bias, const float* __restrict__ bias2,
    float* __restrict__ C)
{
    __shared__ float As[8][128];
    __shared__ float Bs[8][128];

    const int tid = threadIdx.x;
    const int m0 = blockIdx.y * 128;
    const int n0 = blockIdx.x * 128;
    const int tx = tid & 15;
    const int ty = tid >> 4;
    const int lr = tid >> 1;
    const int lc = (tid & 1) * 4;

    unsigned long long acc[8][4];
#pragma unroll
    for (int i = 0; i < 8; i++)
#pragma unroll
        for (int j = 0; j < 4; j++) acc[i][j] = 0ull;

    const float* aLoad = A + (size_t)(m0 + lr) * IN_DIM + lc;
    const float* bLoad = Bw + (size_t)(n0 + lr) * IN_DIM + lc;

    for (int k0 = 0; k0 < IN_DIM; k0 += 8) {
        float4 av = *reinterpret_cast<const float4*>(aLoad + k0);
        float4 bv = *reinterpret_cast<const float4*>(bLoad + k0);
        As[lc + 0][lr] = av.x; As[lc + 1][lr] = av.y;
        As[lc + 2][lr] = av.z; As[lc + 3][lr] = av.w;
        Bs[lc + 0][lr] = bv.x; Bs[lc + 1][lr] = bv.y;
        Bs[lc + 2][lr] = bv.z; Bs[lc + 3][lr] = bv.w;
        __syncthreads();

#pragma unroll
        for (int k = 0; k < 8; k++) {
            float4 a0 = *reinterpret_cast<const float4*>(&As[k][ty * 8]);
            float4 a1 = *reinterpret_cast<const float4*>(&As[k][ty * 8 + 4]);
            ulonglong2 b01 = *reinterpret_cast<const ulonglong2*>(&Bs[k][tx * 8]);
            ulonglong2 b23 = *reinterpret_cast<const ulonglong2*>(&Bs[k][tx * 8 + 4]);
            float a[8] = {a0.x, a0.y, a0.z, a0.w, a1.x, a1.y, a1.z, a1.w};
#pragma unroll
            for (int i = 0; i < 8; i++) {
                unsigned long long a2 = pack2(a[i], a[i]);
                acc[i][0] = ffma2(a2, b01.x, acc[i][0]);
                acc[i][1] = ffma2(a2, b01.y, acc[i][1]);
                acc[i][2] = ffma2(a2, b23.x, acc[i][2]);
                acc[i][3] = ffma2(a2, b23.y, acc[i][3]);
            }
        }
        __syncthreads();
    }

    float bb[8];
#pragma unroll
    for (int j = 0; j < 8; j++)
        bb[j] = bias[n0 + tx * 8 + j] + bias2[n0 + tx * 8 + j];

#pragma unroll
    for (int i = 0; i < 8; i++) {
        float c[8];
#pragma unroll
        for (int j = 0; j < 4; j++) {
            float2 v = unpack2(acc[i][j]);
            c[2 * j + 0] = v.x + bb[2 * j + 0];
            c[2 * j + 1] = v.y + bb[2 * j + 1];
        }
        float* cp = C + (size_t)(m0 + ty * 8 + i) * H_DIM + n0 + tx * 8;
        *reinterpret_cast<float4*>(cp + 0) = make_float4(c[0], c[1], c[2], c[3]);
        *reinterpret_cast<float4*>(cp + 4) = make_float4(c[4], c[5], c[6], c[7]);
    }
}

// ---------------------------------------------------------------------------
// Phase 2: persistent HMMA recurrence (EXACT R13 structure, 256 threads,
// m32xn32 warp tile, 4-way k split) + GROUP-LOCAL step barrier:
// 4 independent m-group chains of 32 CTAs each.
// ---------------------------------------------------------------------------
__global__ __launch_bounds__(256, 1) void rnn_hmma(
    float* __restrict__ out)
{
    extern __shared__ char sm[];
    const uint32_t sb = smem_to_u32(sm);
    const int tid = threadIdx.x;
    const int wid = tid >> 5;
    const int lane = tid & 31;
    const int n0 = blockIdx.x * 32;
    const int grp = blockIdx.y;
    const int m0 = grp * 64;
    const int mt2 = wid & 1;    // m32 tile (rows mt2*32 .. +32)
    const int kq = wid >> 1;    // k-quarter within each 128-k chunk
    const int g = lane >> 2;
    const int tig = lane & 3;

    // One-time: load resident Wh hi/lo slice [32n][1024k] into padded smem.
    for (int i = 0; i < 16; i++) {
        int u = tid + 256 * i;               // 0..4095 uint4 units per half
        int n = u >> 7;                      // 0..31
        int kqd = (u & 127) * 8;             // 0..1016
        uint4 vh = *reinterpret_cast<const uint4*>(&g_Wh_hi[(size_t)(n0 + n) * H_DIM + kqd]);
        uint4 vl = *reinterpret_cast<const uint4*>(&g_Wh_lo[(size_t)(n0 + n) * H_DIM + kqd]);
        *reinterpret_cast<uint4*>(sm + SM_BHI + n * B_ROW_BYTES + kqd * 2) = vh;
        *reinterpret_cast<uint4*>(sm + SM_BLO + n * B_ROW_BYTES + kqd * 2) = vl;
    }
    __syncthreads();

    // ldmatrix lane-address components (proven mappings).
    const uint32_t aByte0 =
        (uint32_t)((mt2 * 32 + (lane & 7) + ((lane >> 3) & 1) * 8) * A_ROW_BYTES
                   + ((lane >> 4) & 1) * 16 + kq * 64);
    const uint32_t aByte1 = aByte0 + 16 * A_ROW_BYTES;
    const uint32_t bRow = (uint32_t)((lane & 7) + ((lane >> 4) & 1) * 8);
    const uint32_t bKof = ((lane >> 3) & 1) * 16;
    const uint32_t bByte0 = bRow * B_ROW_BYTES + bKof;
    const uint32_t bByte1 = (bRow + 16) * B_ROW_BYTES + bKof;

    // Uniform epilogue coordinates: 1 row x 8 cols per thread.
    const int er = tid >> 2;             // 0..63
    const int ec = (tid & 3) * 8;        // col offset 0,8,16,24
    const int erow = m0 + er;

    for (int t = 0; t < T_DIM; t++) {
        const int pb = t & 1;
        const __nv_bfloat16* Ah = g_h_hi[pb] + (size_t)m0 * H_DIM;
        const __nv_bfloat16* Al = g_h_lo[pb] + (size_t)m0 * H_DIM;

        // Hoisted xi loads (DRAM latency hides under the whole kc loop).
        float* outT = out + (size_t)t * BH;
        float* xp = &outT[(size_t)erow * H_DIM + n0 + ec];
        const float4 xv0 = __ldcg(reinterpret_cast<const float4*>(xp));
        const float4 xv1 = __ldcg(reinterpret_cast<const float4*>(xp + 4));

        float d[2][4][4];
#pragma unroll
        for (int t2 = 0; t2 < 2; t2++)
#pragma unroll
            for (int nt = 0; nt < 4; nt++)
#pragma unroll
                for (int e = 0; e < 4; e++) d[t2][nt][e] = 0.0f;

        // Prefetch chunk 0 (A [64 rows][128 k] hi+lo, coalesced uint4)
        uint4 rh[4], rl[4];
#pragma unroll
        for (int i = 0; i < 4; i++) {
            int u = tid + 256 * i;           // 0..1023
            int rrow = u >> 4;               // 0..63
            int kqd = (u & 15) * 8;          // 0..120
            rh[i] = *reinterpret_cast<const uint4*>(&Ah[(size_t)rrow * H_DIM + kqd]);
            rl[i] = *reinterpret_cast<const uint4*>(&Al[(size_t)rrow * H_DIM + kqd]);
        }

        for (int kc = 0; kc < 8; kc++) {
            const int buf = kc & 1;
            char* ah_s = sm + SM_A_HI + buf * A_BUF;
            char* al_s = sm + SM_A_LO + buf * A_BUF;
            // STS (conflict-free: contiguous 16B within padded rows)
#pragma unroll
            for (int i = 0; i < 4; i++) {
                int u = tid + 256 * i;
                int rrow = u >> 4;
                int kqd = (u & 15) * 8;
                *reinterpret_cast<uint4*>(ah_s + rrow * A_ROW_BYTES + kqd * 2) = rh[i];
                *reinterpret_cast<uint4*>(al_s + rrow * A_ROW_BYTES + kqd * 2) = rl[i];
            }
            __syncthreads();
            // Prefetch next chunk (latency hidden by the mma work below)
            if (kc + 1 < 8) {
                const int kb = (kc + 1) * 128;
#pragma unroll
                for (int i = 0; i < 4; i++) {
                    int u = tid + 256 * i;
                    int rrow = u >> 4;
                    int kqd = (u & 15) * 8;
                    rh[i] = *reinterpret_cast<const uint4*>(&Ah[(size_t)rrow * H_DIM + kb + kqd]);
                    rl[i] = *reinterpret_cast<const uint4*>(&Al[(size_t)rrow * H_DIM + kb + kqd]);
                }
            }
            // Compute this chunk: 2 k16 steps on this warp's k-quarter.
            const uint32_t ah0 = sb + SM_A_HI + buf * A_BUF + aByte0;
            const uint32_t ah1 = sb + SM_A_HI + buf * A_BUF + aByte1;
            const uint32_t al0 = sb + SM_A_LO + buf * A_BUF + aByte0;
            const uint32_t al1 = sb + SM_A_LO + buf * A_BUF + aByte1;
            const uint32_t bkB = (uint32_t)(kc * 256 + kq * 64);
#pragma unroll
            for (int ks = 0; ks < 2; ks++) {
                uint32_t a_hi0[4], a_hi1[4], a_lo0[4], a_lo1[4];
                uint32_t b_h[8], b_l[8];
                ldsm4(a_hi0, ah0 + ks * 32);
                ldsm4(a_hi1, ah1 + ks * 32);
                ldsm4(a_lo0, al0 + ks * 32);
                ldsm4(a_lo1, al1 + ks * 32);
                ldsm4(b_h,     sb + SM_BHI + bByte0 + bkB + ks * 32);
                ldsm4(b_h + 4, sb + SM_BHI + bByte1 + bkB + ks * 32);
                ldsm4(b_l,     sb + SM_BLO + bByte0 + bkB + ks * 32);
                ldsm4(b_l + 4, sb + SM_BLO + bByte1 + bkB + ks * 32);
                // Term-major: hi*hi (8), lo*hi (8), hi*lo (8)
#pragma unroll
                for (int nt = 0; nt < 4; nt++) {
                    const uint32_t* ph = &b_h[(nt >> 1) * 4 + (nt & 1) * 2];
                    mma_bf16(d[0][nt], a_hi0, ph);
                    mma_bf16(d[1][nt], a_hi1, ph);
                }
#pragma unroll
                for (int nt = 0; nt < 4; nt++) {
                    const uint32_t* ph = &b_h[(nt >> 1) * 4 + (nt & 1) * 2];
                    mma_bf16(d[0][nt], a_lo0, ph);
                    mma_bf16(d[1][nt], a_lo1, ph);
                }
#pragma unroll
                for (int nt = 0; nt < 4; nt++) {
                    const uint32_t* pl = &b_l[(nt >> 1) * 4 + (nt & 1) * 2];
                    mma_bf16(d[0][nt], a_hi0, pl);
                    mma_bf16(d[1][nt], a_hi1, pl);
                }
            }
        }
        __syncthreads();

        // Publish all 4 k-quarter partials to padded smem buffers (8B aligned).
#pragma unroll
        for (int t2 = 0; t2 < 2; t2++)
#pragma unroll
            for (int nt = 0; nt < 4; nt++)
#pragma unroll
                for (int rp = 0; rp < 2; rp++) {
                    const int prow = mt2 * 32 + t2 * 16 + g + rp * 8;
                    *reinterpret_cast<float2*>(
                        sm + SM_RED + kq * QBUF_BYTES + prow * RED_ROW_BYTES
                        + (nt * 8 + tig * 2) * 4) =
                        make_float2(d[t2][nt][rp * 2], d[t2][nt][rp * 2 + 1]);
                }
        __syncthreads();

        // Uniform reduce + epilogue: each thread 1 row x 8 cols (16B aligned).
        {
            const int pb1 = pb ^ 1;
            float4 sA = make_float4(0.f, 0.f, 0.f, 0.f);
            float4 sB = make_float4(0.f, 0.f, 0.f, 0.f);
#pragma unroll
            for (int q = 0; q < 4; q++) {
                const char* base = sm + SM_RED + q * QBUF_BYTES
                                 + er * RED_ROW_BYTES + ec * 4;
                float4 pA = *reinterpret_cast<const float4*>(base);
                float4 pB = *reinterpret_cast<const float4*>(base + 16);
                sA.x += pA.x; sA.y += pA.y; sA.z += pA.z; sA.w += pA.w;
                sB.x += pB.x; sB.y += pB.y; sB.z += pB.z; sB.w += pB.w;
            }
            float ov[8];
            ov[0] = tanhf(sA.x + xv0.x); ov[1] = tanhf(sA.y + xv0.y);
            ov[2] = tanhf(sA.z + xv0.z); ov[3] = tanhf(sA.w + xv0.w);
            ov[4] = tanhf(sB.x + xv1.x); ov[5] = tanhf(sB.y + xv1.y);
            ov[6] = tanhf(sB.z + xv1.z); ov[7] = tanhf(sB.w + xv1.w);

            *reinterpret_cast<float4*>(xp)     = make_float4(ov[0], ov[1], ov[2], ov[3]);
            *reinterpret_cast<float4*>(xp + 4) = make_float4(ov[4], ov[5], ov[6], ov[7]);

            unsigned short hh[8], ll[8];
#pragma unroll
            for (int e = 0; e < 8; e++) {
                __nv_bfloat16 hb = __float2bfloat16(ov[e]);
                __nv_bfloat16 lb = __float2bfloat16(ov[e] - __bfloat162float(hb));
                hh[e] = *reinterpret_cast<unsigned short*>(&hb);
                ll[e] = *reinterpret_cast<unsigned short*>(&lb);
            }
            const size_t hoff = (size_t)erow * H_DIM + n0 + ec;
            *reinterpret_cast<uint4*>(&g_h_hi[pb1][hoff]) =
                *reinterpret_cast<const uint4*>(hh);
            *reinterpret_cast<uint4*>(&g_h_lo[pb1][hoff]) =
                *reinterpret_cast<const uint4*>(ll);
        }

        // GROUP-LOCAL step barrier: only this m-group's 32 CTAs.
        if (t + 1 < T_DIM) {
            __syncthreads();
            __threadfence();
            if (tid == 0) {
                int* cp = &g_cnt[grp * T_DIM + t];
                atomicAdd(cp, 1);
                volatile int* p = cp;
                while (*p < GRP_CTAS) { }
            }
            __syncthreads();
            __threadfence();
        }
    }
}

// ---------------------------------------------------------------------------
// Launch
// inputs: 0=x [T,B,IN], 1=h [B,H], 2=Wi_w [H,IN], 3=Wi_b [H],
//         4=Wh_w [H,H], 5=Wh_b [H];  output: hiddens [T,B,H]
// ---------------------------------------------------------------------------
extern "C" void kernel_launch(void* const* d_in, const int* in_sizes, int n_in,
                              void* d_out, int out_size) {
    const float* x   = (const float*)d_in[0];
    const float* h0  = (const float*)d_in[1];
    const float* Wi  = (const float*)d_in[2];
    const float* bi  = (const float*)d_in[3];
    const float* Wh  = (const float*)d_in[4];
    const float* bh  = (const float*)d_in[5];
    float* out = (float*)d_out;

    static bool attr_set = false;
    if (!attr_set) {
        cudaFuncSetAttribute(rnn_hmma,
                             cudaFuncAttributeMaxDynamicSharedMemorySize,
                             SMEM_P2);
        attr_set = true;
    }

    // Launch slot 1: reset counters; slot 2: split Wh+h0 (full coverage);
    // slot 3: xi GEMM; slot 4: rnn_hmma (the ncu-profiled slot).
    reset_kernel<<<4, 256>>>();
    split_all_kernel<<<SPLIT_WH_BLOCKS + SPLIT_H0_BLOCKS, 256>>>(Wh, h0);
    gemm_xi_kernel<<<dim3(H_DIM / 128, M1 / 128), 256>>>(x, Wi, bi, bh, out);
    rnn_hmma<<<dim3(32, 4), 256, SMEM_P2>>>(out);
}